// round 15
// baseline (speedup 1.0000x reference)
#include <cuda_runtime.h>

#define NNODE 50000
#define NEDGE 800000
#define ETOT  (NNODE + NEDGE)   // edges + self loops
#define FEAT  128               // H*C
#define HH    4
#define NEG_SLOPE 0.2f

// ---- scratch (static device globals; no allocation allowed) ----
__device__ float g_xl[NNODE * FEAT];   // 25.6 MB
__device__ float g_xr[NNODE * FEAT];   // 25.6 MB
__device__ float g_ex[ETOT * HH];      // 13.6 MB  exp(logit) per edge/head
__device__ float g_den[NNODE * HH];    // softmax denominators
__device__ float g_alpha_sink[ETOT * HH];  // fallback alpha target
__device__ int   g_ei32[2 * NEDGE];    // normalized int32 edge index
__device__ int   g_is64;               // detected dtype flag

// ---------------------------------------------------------------
// K-1a: detect edge_index dtype (int64 vs int32).
// ---------------------------------------------------------------
__global__ void k_detect(const void* __restrict__ ei) {
    if (threadIdx.x == 0 && blockIdx.x == 0) {
        const long long* p64 = (const long long*)ei;
        int is64 = 1;
        #pragma unroll
        for (int i = 0; i < 32; i++) {
            long long v = p64[i];
            if (v < 0 || v >= NNODE) { is64 = 0; break; }
        }
        g_is64 = is64;
    }
}

// ---------------------------------------------------------------
// K-1b (MERGED): normalize edge index to int32 AND zero the
// output accumulator + denominators, one grid.
// ---------------------------------------------------------------
__global__ void k_prep(const void* __restrict__ ei, float* __restrict__ out_acc) {
    int i = blockIdx.x * blockDim.x + threadIdx.x;
    if (i < 2 * NEDGE) {
        int v = g_is64 ? (int)((const long long*)ei)[i]
                       : ((const int*)ei)[i];
        g_ei32[i] = v;
    }
    if (i < NNODE * FEAT) out_acc[i] = 0.0f;
    if (i < NNODE * HH)   g_den[i]   = 0.0f;
}

// ---------------------------------------------------------------
// K1: FUSED dual projection GEMM, smem-traffic-optimized.
// x tile stored TRANSPOSED (xs_t[k][row]): the 'a' fetch is one
// broadcast-friendly LDS.128. Per-warp smem bytes per kk:
// ~2560B -> ~1050B, balancing LDS with the FFMA floor.
// ---------------------------------------------------------------
__global__ void k_gemm(const float* __restrict__ x,
                       const float* __restrict__ Wl,
                       const float* __restrict__ Wr) {
    __shared__ float xs_t[16][68];   // [k][row], +4 pad
    __shared__ float wsl[16][128];
    __shared__ float wsr[16][128];

    const int tid = threadIdx.x;
    const int tx  = tid & 15;
    const int ty  = tid >> 4;
    const int row0 = blockIdx.x * 64;

    float accl[4][8] = {};
    float accr[4][8] = {};

    for (int k0 = 0; k0 < 128; k0 += 16) {
        {
            int r = tid >> 2;
            int c = (tid & 3) * 4;
            float4 v = make_float4(0.f, 0.f, 0.f, 0.f);
            if (row0 + r < NNODE)
                v = *(const float4*)(x + (size_t)(row0 + r) * FEAT + k0 + c);
            xs_t[c    ][r] = v.x;
            xs_t[c + 1][r] = v.y;
            xs_t[c + 2][r] = v.z;
            xs_t[c + 3][r] = v.w;
        }
        {
            int r = tid >> 4;
            int c = (tid & 15) * 8;
            size_t off = (size_t)(k0 + r) * FEAT + c;
            *(float4*)&wsl[r][c]     = *(const float4*)(Wl + off);
            *(float4*)&wsl[r][c + 4] = *(const float4*)(Wl + off + 4);
            *(float4*)&wsr[r][c]     = *(const float4*)(Wr + off);
            *(float4*)&wsr[r][c + 4] = *(const float4*)(Wr + off + 4);
        }
        __syncthreads();

        #pragma unroll
        for (int kk = 0; kk < 16; kk++) {
            float4 av  = *(const float4*)&xs_t[kk][ty * 4];
            float4 bl0 = *(const float4*)&wsl[kk][tx * 8];
            float4 bl1 = *(const float4*)&wsl[kk][tx * 8 + 4];
            float4 br0 = *(const float4*)&wsr[kk][tx * 8];
            float4 br1 = *(const float4*)&wsr[kk][tx * 8 + 4];

            float a[4]  = {av.x, av.y, av.z, av.w};
            float bl[8] = {bl0.x, bl0.y, bl0.z, bl0.w, bl1.x, bl1.y, bl1.z, bl1.w};
            float br[8] = {br0.x, br0.y, br0.z, br0.w, br1.x, br1.y, br1.z, br1.w};

            #pragma unroll
            for (int i = 0; i < 4; i++)
                #pragma unroll
                for (int j = 0; j < 8; j++) {
                    accl[i][j] += a[i] * bl[j];
                    accr[i][j] += a[i] * br[j];
                }
        }
        __syncthreads();
    }

    #pragma unroll
    for (int i = 0; i < 4; i++) {
        int r = row0 + ty * 4 + i;
        if (r < NNODE) {
            size_t off = (size_t)r * FEAT + tx * 8;
            *(float4*)(g_xl + off)     = make_float4(accl[i][0], accl[i][1], accl[i][2], accl[i][3]);
            *(float4*)(g_xl + off + 4) = make_float4(accl[i][4], accl[i][5], accl[i][6], accl[i][7]);
            *(float4*)(g_xr + off)     = make_float4(accr[i][0], accr[i][1], accr[i][2], accr[i][3]);
            *(float4*)(g_xr + off + 4) = make_float4(accr[i][4], accr[i][5], accr[i][6], accr[i][7]);
        }
    }
}

// ---------------------------------------------------------------
// K2: one warp per edge.  logits -> exp; lane 0 packs all 4 heads
// into ONE st.global.v4 (g_ex) and ONE red.global.add.v4.f32
// (g_den): 4x fewer RMW ops + stores vs scalar-per-head.
// Max-subtraction elided (algebraically exact here).
// ---------------------------------------------------------------
__global__ void k_edge_logits(const float* __restrict__ att) {
    int w    = (blockIdx.x * blockDim.x + threadIdx.x) >> 5;
    int lane = threadIdx.x & 31;
    if (w >= ETOT) return;

    int s = 0, d = 0;
    if (lane == 0) {
        if (w < NEDGE) { s = g_ei32[w]; d = g_ei32[NEDGE + w]; }
        else           { s = d = w - NEDGE; }
    }
    s = __shfl_sync(0xffffffffu, s, 0);
    d = __shfl_sync(0xffffffffu, d, 0);

    float4 a = ((const float4*)g_xl)[(size_t)s * 32 + lane];
    float4 b = ((const float4*)g_xr)[(size_t)d * 32 + lane];
    float4 v;
    v.x = a.x + b.x; v.y = a.y + b.y; v.z = a.z + b.z; v.w = a.w + b.w;
    v.x = v.x > 0.f ? v.x : NEG_SLOPE * v.x;
    v.y = v.y > 0.f ? v.y : NEG_SLOPE * v.y;
    v.z = v.z > 0.f ? v.z : NEG_SLOPE * v.z;
    v.w = v.w > 0.f ? v.w : NEG_SLOPE * v.w;

    float4 at = __ldg((const float4*)att + lane);
    float p = v.x * at.x + v.y * at.y + v.z * at.z + v.w * at.w;

    p += __shfl_down_sync(0xffffffffu, p, 4, 8);
    p += __shfl_down_sync(0xffffffffu, p, 2, 8);
    p += __shfl_down_sync(0xffffffffu, p, 1, 8);

    // head-leader lanes 0,8,16,24 hold p for heads 0..3
    float ex = __expf(p);
    float e0 = __shfl_sync(0xffffffffu, ex, 0);
    float e1 = __shfl_sync(0xffffffffu, ex, 8);
    float e2 = __shfl_sync(0xffffffffu, ex, 16);
    float e3 = __shfl_sync(0xffffffffu, ex, 24);

    if (lane == 0) {
        ((float4*)g_ex)[w] = make_float4(e0, e1, e2, e3);
        float* dp = g_den + (size_t)d * HH;
        asm volatile("red.global.add.v4.f32 [%0], {%1,%2,%3,%4};"
                     :: "l"(dp), "f"(e0), "f"(e1), "f"(e2), "f"(e3)
                     : "memory");
    }
}

// ---------------------------------------------------------------
// K3: one warp per edge.  alpha = ex/den; write alpha output
// (alpha_out == nullptr -> discard to g_alpha_sink); scatter
// alpha * xl[src] with red.add.v4.f32 (4x fewer L2 RMW ops).
// ---------------------------------------------------------------
__global__ void k_edge_scatter(float* __restrict__ out_acc,
                               float* __restrict__ alpha_out) {
    int w    = (blockIdx.x * blockDim.x + threadIdx.x) >> 5;
    int lane = threadIdx.x & 31;
    if (w >= ETOT) return;

    int s = 0, d = 0;
    if (lane == 0) {
        if (w < NEDGE) { s = g_ei32[w]; d = g_ei32[NEDGE + w]; }
        else           { s = d = w - NEDGE; }
    }
    s = __shfl_sync(0xffffffffu, s, 0);
    d = __shfl_sync(0xffffffffu, d, 0);

    int h = lane >> 3;
    float ex  = g_ex[(size_t)w * HH + h];
    float den = g_den[(size_t)d * HH + h];
    float alpha = ex / den;

    if ((lane & 7) == 0) {
        float* ap = alpha_out ? alpha_out : g_alpha_sink;
        ap[(size_t)w * HH + h] = alpha;
    }

    float4 a = ((const float4*)g_xl)[(size_t)s * 32 + lane];
    float* p = out_acc + (size_t)d * FEAT + lane * 4;
    asm volatile("red.global.add.v4.f32 [%0], {%1,%2,%3,%4};"
                 :: "l"(p), "f"(a.x * alpha), "f"(a.y * alpha),
                    "f"(a.z * alpha), "f"(a.w * alpha)
                 : "memory");
}

// ---------------------------------------------------------------
// K4: out = relu(acc + bias), float4-vectorized
// ---------------------------------------------------------------
__global__ void k_final(float4* __restrict__ out, const float4* __restrict__ bias) {
    int i = blockIdx.x * blockDim.x + threadIdx.x;
    if (i < NNODE * (FEAT / 4)) {
        float4 v = out[i];
        float4 b = __ldg(bias + (i & (FEAT / 4 - 1)));
        v.x = v.x + b.x; v.y = v.y + b.y; v.z = v.z + b.z; v.w = v.w + b.w;
        v.x = v.x > 0.f ? v.x : 0.f;
        v.y = v.y > 0.f ? v.y : 0.f;
        v.z = v.z > 0.f ? v.z : 0.f;
        v.w = v.w > 0.f ? v.w : 0.f;
        out[i] = v;
    }
}

// ---------------------------------------------------------------
extern "C" void kernel_launch(void* const* d_in, const int* in_sizes, int n_in,
                              void* d_out, int out_size) {
    const float* x    = (const float*)d_in[0];
    const void*  ei   = d_in[1];                    // int32 or int64, detected on device
    const float* Wl   = (const float*)d_in[2];
    const float* Wr   = (const float*)d_in[3];
    const float* att  = (const float*)d_in[4];
    const float* bias = (const float*)d_in[5];

    float* out = (float*)d_out;                     // [N, 128]
    float* alpha_out = (out_size >= NNODE * FEAT + ETOT * HH)
                     ? out + (size_t)NNODE * FEAT   // [ETOT, 4]
                     : nullptr;

    k_detect<<<1, 32>>>(ei);
    k_prep<<<(NNODE * FEAT + 255) / 256, 256>>>(ei, out);   // convert + zero, one sweep

    k_gemm<<<(NNODE + 63) / 64, 256>>>(x, Wl, Wr);

    int edge_blocks = (ETOT * 32 + 255) / 256;      // 1 warp per edge
    k_edge_logits<<<edge_blocks, 256>>>(att);
    k_edge_scatter<<<edge_blocks, 256>>>(out, alpha_out);

    k_final<<<(NNODE * FEAT / 4 + 255) / 256, 256>>>((float4*)out, (const float4*)bias);
}

// round 16
// speedup vs baseline: 1.1727x; 1.1727x over previous
#include <cuda_runtime.h>

#define NNODE 50000
#define NEDGE 800000
#define ETOT  (NNODE + NEDGE)   // edges + self loops
#define FEAT  128               // H*C
#define HH    4
#define NEG_SLOPE 0.2f

// ---- scratch (static device globals; no allocation allowed) ----
__device__ float g_xl[NNODE * FEAT];     // 25.6 MB
__device__ float g_xr[NNODE * FEAT];     // 25.6 MB
__device__ float g_ex[ETOT * HH];        // 13.6 MB exp(logit) per edge/head
__device__ float g_alpha_sink[ETOT * HH];
__device__ int   g_ei32[2 * NEDGE];      // normalized int32 edge index
__device__ int   g_is64;
__device__ int   g_cnt[NNODE];           // histogram -> cursor (after scan holds row start)
__device__ int   g_rowstart[NNODE];      // CSR row offsets
__device__ int2  g_csr[ETOT];            // (src, edge_id) grouped by dst

// ---------------------------------------------------------------
// K-1a: detect edge_index dtype (int64 vs int32).
// ---------------------------------------------------------------
__global__ void k_detect(const void* __restrict__ ei) {
    if (threadIdx.x == 0 && blockIdx.x == 0) {
        const long long* p64 = (const long long*)ei;
        int is64 = 1;
        #pragma unroll
        for (int i = 0; i < 32; i++) {
            long long v = p64[i];
            if (v < 0 || v >= NNODE) { is64 = 0; break; }
        }
        g_is64 = is64;
    }
}

// ---------------------------------------------------------------
// K-1b: normalize edge index to int32; zero dst histogram.
// ---------------------------------------------------------------
__global__ void k_prep(const void* __restrict__ ei) {
    int i = blockIdx.x * blockDim.x + threadIdx.x;
    if (i < 2 * NEDGE) {
        int v = g_is64 ? (int)((const long long*)ei)[i]
                       : ((const int*)ei)[i];
        g_ei32[i] = v;
    }
    if (i < NNODE) g_cnt[i] = 0;
}

// ---------------------------------------------------------------
// K1: FUSED dual projection GEMM (transposed x tile — verified
// improvement R15: no longer the top launch).
// ---------------------------------------------------------------
__global__ void k_gemm(const float* __restrict__ x,
                       const float* __restrict__ Wl,
                       const float* __restrict__ Wr) {
    __shared__ float xs_t[16][68];
    __shared__ float wsl[16][128];
    __shared__ float wsr[16][128];

    const int tid = threadIdx.x;
    const int tx  = tid & 15;
    const int ty  = tid >> 4;
    const int row0 = blockIdx.x * 64;

    float accl[4][8] = {};
    float accr[4][8] = {};

    for (int k0 = 0; k0 < 128; k0 += 16) {
        {
            int r = tid >> 2;
            int c = (tid & 3) * 4;
            float4 v = make_float4(0.f, 0.f, 0.f, 0.f);
            if (row0 + r < NNODE)
                v = *(const float4*)(x + (size_t)(row0 + r) * FEAT + k0 + c);
            xs_t[c    ][r] = v.x;
            xs_t[c + 1][r] = v.y;
            xs_t[c + 2][r] = v.z;
            xs_t[c + 3][r] = v.w;
        }
        {
            int r = tid >> 4;
            int c = (tid & 15) * 8;
            size_t off = (size_t)(k0 + r) * FEAT + c;
            *(float4*)&wsl[r][c]     = *(const float4*)(Wl + off);
            *(float4*)&wsl[r][c + 4] = *(const float4*)(Wl + off + 4);
            *(float4*)&wsr[r][c]     = *(const float4*)(Wr + off);
            *(float4*)&wsr[r][c + 4] = *(const float4*)(Wr + off + 4);
        }
        __syncthreads();

        #pragma unroll
        for (int kk = 0; kk < 16; kk++) {
            float4 av  = *(const float4*)&xs_t[kk][ty * 4];
            float4 bl0 = *(const float4*)&wsl[kk][tx * 8];
            float4 bl1 = *(const float4*)&wsl[kk][tx * 8 + 4];
            float4 br0 = *(const float4*)&wsr[kk][tx * 8];
            float4 br1 = *(const float4*)&wsr[kk][tx * 8 + 4];

            float a[4]  = {av.x, av.y, av.z, av.w};
            float bl[8] = {bl0.x, bl0.y, bl0.z, bl0.w, bl1.x, bl1.y, bl1.z, bl1.w};
            float br[8] = {br0.x, br0.y, br0.z, br0.w, br1.x, br1.y, br1.z, br1.w};

            #pragma unroll
            for (int i = 0; i < 4; i++)
                #pragma unroll
                for (int j = 0; j < 8; j++) {
                    accl[i][j] += a[i] * bl[j];
                    accr[i][j] += a[i] * br[j];
                }
        }
        __syncthreads();
    }

    #pragma unroll
    for (int i = 0; i < 4; i++) {
        int r = row0 + ty * 4 + i;
        if (r < NNODE) {
            size_t off = (size_t)r * FEAT + tx * 8;
            *(float4*)(g_xl + off)     = make_float4(accl[i][0], accl[i][1], accl[i][2], accl[i][3]);
            *(float4*)(g_xl + off + 4) = make_float4(accl[i][4], accl[i][5], accl[i][6], accl[i][7]);
            *(float4*)(g_xr + off)     = make_float4(accr[i][0], accr[i][1], accr[i][2], accr[i][3]);
            *(float4*)(g_xr + off + 4) = make_float4(accr[i][4], accr[i][5], accr[i][6], accr[i][7]);
        }
    }
}

// ---------------------------------------------------------------
// K2a: histogram of destination nodes (ETOT edges incl self loops)
// ---------------------------------------------------------------
__global__ void k_hist() {
    int w = blockIdx.x * blockDim.x + threadIdx.x;
    if (w >= ETOT) return;
    int d = (w < NEDGE) ? g_ei32[NEDGE + w] : w - NEDGE;
    atomicAdd(&g_cnt[d], 1);
}

// ---------------------------------------------------------------
// K2b: exclusive scan of counts (single block, shfl-based).
// Writes g_rowstart[i] and re-initializes g_cnt[i] as fill cursor.
// ---------------------------------------------------------------
__global__ void k_scan() {
    __shared__ int wsum[32];
    __shared__ int stotal;
    int tid = threadIdx.x, lane = tid & 31, wid = tid >> 5;
    if (tid == 0) stotal = 0;
    __syncthreads();

    for (int base = 0; base < NNODE; base += 1024) {
        int i = base + tid;
        int v = (i < NNODE) ? g_cnt[i] : 0;
        int x = v;
        #pragma unroll
        for (int off = 1; off < 32; off <<= 1) {
            int t = __shfl_up_sync(0xffffffffu, x, off);
            if (lane >= off) x += t;
        }
        if (lane == 31) wsum[wid] = x;
        __syncthreads();
        if (wid == 0) {
            int y = wsum[lane];
            #pragma unroll
            for (int off = 1; off < 32; off <<= 1) {
                int t = __shfl_up_sync(0xffffffffu, y, off);
                if (lane >= off) y += t;
            }
            wsum[lane] = y;                // inclusive scan of warp sums
        }
        __syncthreads();
        int woff = wid ? wsum[wid - 1] : 0;
        int excl = stotal + woff + x - v;  // exclusive prefix
        if (i < NNODE) { g_rowstart[i] = excl; g_cnt[i] = excl; }
        int btot = wsum[31];
        __syncthreads();
        if (tid == 0) stotal += btot;
        __syncthreads();
    }
}

// ---------------------------------------------------------------
// K2c: fill CSR slots (cursor = g_cnt, post-scan start offsets)
// ---------------------------------------------------------------
__global__ void k_fill() {
    int w = blockIdx.x * blockDim.x + threadIdx.x;
    if (w >= ETOT) return;
    int s, d;
    if (w < NEDGE) { s = g_ei32[w]; d = g_ei32[NEDGE + w]; }
    else           { s = d = w - NEDGE; }
    int slot = atomicAdd(&g_cnt[d], 1);
    g_csr[slot] = make_int2(s, w);
}

// ---------------------------------------------------------------
// K3: FUSED per-node edge kernel. One warp per dst node:
//   xr[d] loaded once; pass1: ex per edge + den in registers;
//   pass2: alpha, alpha-weighted accumulate of xl[s] in registers;
//   epilogue: out = relu(acc + bias). NO atomics, NO out zeroing,
//   NO final sweep. Lane L: head h=L>>3, channels (L&7)*4..+3.
// ---------------------------------------------------------------
__global__ void k_node(float* __restrict__ out,
                       float* __restrict__ alpha_out,
                       const float* __restrict__ att,
                       const float* __restrict__ bias) {
    int node = (blockIdx.x * blockDim.x + threadIdx.x) >> 5;
    int lane = threadIdx.x & 31;
    if (node >= NNODE) return;

    int start = g_rowstart[node];
    int end   = g_cnt[node];          // cursor after fill == row end

    float4 xr = ((const float4*)g_xr)[(size_t)node * 32 + lane];
    float4 at = __ldg((const float4*)att + lane);
    int grp_leader = lane & ~7;       // 0,8,16,24

    // ---- pass 1: ex per edge, den in registers ----
    float den = 0.f;
    for (int e = start; e < end; e++) {
        int2 sw = g_csr[e];
        float4 a = ((const float4*)g_xl)[(size_t)sw.x * 32 + lane];
        float4 v;
        v.x = a.x + xr.x; v.y = a.y + xr.y; v.z = a.z + xr.z; v.w = a.w + xr.w;
        v.x = v.x > 0.f ? v.x : NEG_SLOPE * v.x;
        v.y = v.y > 0.f ? v.y : NEG_SLOPE * v.y;
        v.z = v.z > 0.f ? v.z : NEG_SLOPE * v.z;
        v.w = v.w > 0.f ? v.w : NEG_SLOPE * v.w;
        float p = v.x * at.x + v.y * at.y + v.z * at.z + v.w * at.w;
        p += __shfl_down_sync(0xffffffffu, p, 4, 8);
        p += __shfl_down_sync(0xffffffffu, p, 2, 8);
        p += __shfl_down_sync(0xffffffffu, p, 1, 8);
        float ex = __expf(p);
        ex = __shfl_sync(0xffffffffu, ex, grp_leader);   // broadcast within head group
        den += ex;
        float e0 = __shfl_sync(0xffffffffu, ex, 0);
        float e1 = __shfl_sync(0xffffffffu, ex, 8);
        float e2 = __shfl_sync(0xffffffffu, ex, 16);
        float e3 = __shfl_sync(0xffffffffu, ex, 24);
        if (lane == 0)
            ((float4*)g_ex)[sw.y] = make_float4(e0, e1, e2, e3);
    }
    float rden = 1.f / den;           // per-lane (head-specific) reciprocal

    // ---- pass 2: alpha + weighted accumulate ----
    int h = lane >> 3;
    float4 acc = make_float4(0.f, 0.f, 0.f, 0.f);
    for (int e = start; e < end; e++) {
        int2 sw = g_csr[e];
        float exh = g_ex[(size_t)sw.y * HH + h];
        float alpha = exh * rden;
        float a0 = __shfl_sync(0xffffffffu, alpha, 0);
        float a1 = __shfl_sync(0xffffffffu, alpha, 8);
        float a2 = __shfl_sync(0xffffffffu, alpha, 16);
        float a3 = __shfl_sync(0xffffffffu, alpha, 24);
        if (lane == 0)
            ((float4*)alpha_out)[sw.y] = make_float4(a0, a1, a2, a3);
        float4 a = ((const float4*)g_xl)[(size_t)sw.x * 32 + lane];
        acc.x += alpha * a.x; acc.y += alpha * a.y;
        acc.z += alpha * a.z; acc.w += alpha * a.w;
    }

    // ---- epilogue: bias + relu, single store ----
    float4 b = __ldg((const float4*)bias + lane);
    acc.x += b.x; acc.y += b.y; acc.z += b.z; acc.w += b.w;
    acc.x = acc.x > 0.f ? acc.x : 0.f;
    acc.y = acc.y > 0.f ? acc.y : 0.f;
    acc.z = acc.z > 0.f ? acc.z : 0.f;
    acc.w = acc.w > 0.f ? acc.w : 0.f;
    ((float4*)out)[(size_t)node * 32 + lane] = acc;
}

// ---------------------------------------------------------------
extern "C" void kernel_launch(void* const* d_in, const int* in_sizes, int n_in,
                              void* d_out, int out_size) {
    const float* x    = (const float*)d_in[0];
    const void*  ei   = d_in[1];
    const float* Wl   = (const float*)d_in[2];
    const float* Wr   = (const float*)d_in[3];
    const float* att  = (const float*)d_in[4];
    const float* bias = (const float*)d_in[5];

    float* out = (float*)d_out;                     // [N, 128]
    float* alpha_out = (out_size >= NNODE * FEAT + ETOT * HH)
                     ? out + (size_t)NNODE * FEAT   // [ETOT, 4]
                     : g_alpha_sink;                // device-symbol addr resolved at launch?  no:
    // note: g_alpha_sink as a device symbol can't be taken on host; guard below
    if (out_size < NNODE * FEAT + ETOT * HH) {
        // fall back: resolve sink address once (host API, outside capture-sensitive ops)
        static float* sink = nullptr;
        if (!sink) cudaGetSymbolAddress((void**)&sink, g_alpha_sink);
        alpha_out = sink;
    }

    k_detect<<<1, 32>>>(ei);
    k_prep<<<(2 * NEDGE + 255) / 256, 256>>>(ei);

    k_gemm<<<(NNODE + 63) / 64, 256>>>(x, Wl, Wr);

    k_hist<<<(ETOT + 255) / 256, 256>>>();
    k_scan<<<1, 1024>>>();
    k_fill<<<(ETOT + 255) / 256, 256>>>();

    k_node<<<(NNODE * 32 + 255) / 256, 256>>>(out, alpha_out, att, bias);
}